// round 14
// baseline (speedup 1.0000x reference)
#include <cuda_runtime.h>
#include <cstdint>
#include <cfloat>

#define NROWS   16000
#define NBANDS  64
#define HIDDEN  512
#define LATENT  256
#define GRP     8
#define GD      32
#define KCB     1024

__device__ float g_hidden[NROWS * HIDDEN];
__device__ float g_loss_part[1024];
__device__ unsigned int g_cnt = 0;

// Packed fragment-quad weights: [kg][n][ctg] float4 = (b_k, b_k+4, r_k, r_k+4)
__device__ float4 g_wtp[163840];
// Packed codebook: [g][kg(4)][cw(1024)][ctg(4)] float4
__device__ float4 g_cbp[GRP * 16384];
__device__ float  g_cnh[GRP * KCB];          // -0.5 * ||c||^2 (exact scale)
// Packed z_e (produced by enc2 epilogue): [row][kg8(32)*4 + slot] float4
__device__ float4 g_zep[NROWS * 128];

// ===========================================================================
// Helpers
// ===========================================================================
__device__ __forceinline__ uint32_t smem_u32(const void* p) {
    uint32_t a;
    asm("{ .reg .u64 t; cvta.to.shared.u64 t, %1; cvt.u32.u64 %0, t; }" : "=r"(a) : "l"(p));
    return a;
}
__device__ __forceinline__ uint32_t tf32_of(float x) {
    uint32_t r;
    asm("cvt.rna.tf32.f32 %0, %1;" : "=r"(r) : "f"(x));
    return r;
}
__device__ __forceinline__ float tf32f(float x) {
    return __uint_as_float(tf32_of(x));
}
__device__ __forceinline__ void cp_async16(uint32_t saddr, const void* g) {
    asm volatile("cp.async.cg.shared.global [%0], [%1], 16;" :: "r"(saddr), "l"(g));
}
#define CP_COMMIT() asm volatile("cp.async.commit_group;" ::: "memory")
#define CP_WAIT0()  asm volatile("cp.async.wait_group 0;" ::: "memory")
#define CP_WAIT1()  asm volatile("cp.async.wait_group 1;" ::: "memory")

__device__ __forceinline__ void mma_tf32(float* c, const uint32_t* a, uint32_t b0, uint32_t b1) {
    asm volatile(
        "mma.sync.aligned.m16n8k8.row.col.f32.tf32.tf32.f32 "
        "{%0,%1,%2,%3}, {%4,%5,%6,%7}, {%8,%9}, {%0,%1,%2,%3};"
        : "+f"(c[0]), "+f"(c[1]), "+f"(c[2]), "+f"(c[3])
        : "r"(a[0]), "r"(a[1]), "r"(a[2]), "r"(a[3]), "r"(b0), "r"(b1));
}

// ===========================================================================
// Single fused split kernel: blocks [0,640) pack weights, [640,672) codebook.
// ===========================================================================
__global__ void split_fused(const float* __restrict__ ew1, const float* __restrict__ ew2,
                            const float* __restrict__ dw1, const float* __restrict__ dw2,
                            const float* __restrict__ cb,
                            float4* __restrict__ wtp, float4* __restrict__ cbp,
                            float* __restrict__ cnh)
{
    if (blockIdx.x < 640) {
        int i = blockIdx.x * 256 + threadIdx.x;
        const float* w; int N, off;
        if      (i < 16384)  { w = ew1; N = 512; off = i; }
        else if (i < 81920)  { w = ew2; N = 256; off = i - 16384; }
        else if (i < 147456) { w = dw1; N = 512; off = i - 81920; }
        else                 { w = dw2; N = 64;  off = i - 147456; }
        int ctg = off & 3;
        int rem = off >> 2;
        int n = rem % N, kg = rem / N;
        float x0 = w[(size_t)(kg * 8 + ctg) * N + n];
        float x1 = w[(size_t)(kg * 8 + 4 + ctg) * N + n];
        float b0 = tf32f(x0);
        float b1 = tf32f(x1);
        float r0 = tf32f(x0 - b0);
        float r1 = tf32f(x1 - b1);
        wtp[i] = make_float4(b0, b1, r0, r1);
    } else {
        int row = (blockIdx.x - 640) * 256 + threadIdx.x;
        if (row >= GRP * KCB) return;
        int g = row >> 10, cw = row & 1023;
        const float* src = cb + (size_t)row * GD;
        float bg[GD], rs[GD], s = 0.0f;
        #pragma unroll
        for (int d = 0; d < GD; d++) {
            float x = src[d];
            bg[d] = tf32f(x);
            rs[d] = tf32f(x - bg[d]);
            s = fmaf(x, x, s);
        }
        cnh[row] = -0.5f * s;
        float4* dst = cbp + (size_t)g * 16384;
        #pragma unroll
        for (int kg = 0; kg < 4; kg++)
            #pragma unroll
            for (int ctg = 0; ctg < 4; ctg++)
                dst[(kg * 1024 + cw) * 4 + ctg] =
                    make_float4(bg[kg * 8 + ctg], bg[kg * 8 + 4 + ctg],
                                rs[kg * 8 + ctg], rs[kg * 8 + 4 + ctg]);
    }
}

// ===========================================================================
// Tensor GEMM (3xtf32), packed-quad B, in-loop A conversion.
// PACKQ: epilogue additionally emits packed fragment-quad C (for VQ's A).
// ===========================================================================
template<int BM, int BN, bool RELU, bool PACKQ>
__global__ __launch_bounds__(256, 2) void tgemm(
    const float* __restrict__ A,
    const float4* __restrict__ Wp,
    const float* __restrict__ bias, float* __restrict__ C,
    float4* __restrict__ Cp,
    int M, int N, int K)
{
    constexpr int BK = 32;
    constexpr int ASTR = 36;
    constexpr int WN = BN / 2, NT = WN / 8;
    constexpr int MT = BM / 64;
    constexpr int ASZ = BM * ASTR;
    constexpr int BSZ4 = 4 * BN * 4;
    constexpr int A_Q = BM / 32;
    constexpr int B_Q = BN / 16;

    extern __shared__ __align__(16) float sm[];
    float*  AsBuf[2] = { sm, sm + ASZ };
    float4* BpBuf[2] = { (float4*)(sm + 2 * ASZ), (float4*)(sm + 2 * ASZ) + BSZ4 };

    const int tid = threadIdx.x;
    const int wid = tid >> 5;
    const int lane = tid & 31;
    const int grp = lane >> 2;
    const int ctg = lane & 3;
    const int wy  = wid & 3;
    const int wx  = wid >> 2;
    const int m0  = blockIdx.y * BM;
    const int n0  = blockIdx.x * BN;

    float acc[MT][NT][4];
    #pragma unroll
    for (int mt = 0; mt < MT; mt++)
        #pragma unroll
        for (int nt = 0; nt < NT; nt++)
            #pragma unroll
            for (int q = 0; q < 4; q++) acc[mt][nt][q] = 0.0f;

    auto copy_chunk = [&](int ch, int buf) {
        const int k0 = ch * BK;
        const int kg0 = ch * 4;
        uint32_t as = smem_u32(AsBuf[buf]);
        uint32_t bs = smem_u32(BpBuf[buf]);
        #pragma unroll
        for (int u = 0; u < A_Q; u++) {
            int f = tid + u * 256;
            int r = f >> 3, q = f & 7;
            cp_async16(as + (uint32_t)(r * ASTR + q * 4) * 4,
                       &A[(size_t)(m0 + r) * K + k0 + q * 4]);
        }
        #pragma unroll
        for (int u = 0; u < B_Q; u++) {
            int f = tid + u * 256;
            int kgl = f / (BN * 4);
            int rem = f % (BN * 4);
            int nl = rem >> 2, c = rem & 3;
            cp_async16(bs + (uint32_t)f * 16,
                       &Wp[((size_t)(kg0 + kgl) * N + n0 + nl) * 4 + c]);
        }
        CP_COMMIT();
    };

    auto compute = [&](int buf) {
        const float*  As = AsBuf[buf];
        const float4* Bp = BpBuf[buf];
        #pragma unroll
        for (int ks = 0; ks < 4; ks++) {
            const int k8 = ks * 8;
            uint32_t abig[MT][4], ares[MT][4];
            #pragma unroll
            for (int mt = 0; mt < MT; mt++) {
                const int rb = wy * (BM / 4) + mt * 16;
                float af[4];
                af[0] = As[(rb + grp) * ASTR + k8 + ctg];
                af[1] = As[(rb + 8 + grp) * ASTR + k8 + ctg];
                af[2] = As[(rb + grp) * ASTR + k8 + 4 + ctg];
                af[3] = As[(rb + 8 + grp) * ASTR + k8 + 4 + ctg];
                #pragma unroll
                for (int q = 0; q < 4; q++) {
                    abig[mt][q] = tf32_of(af[q]);
                    ares[mt][q] = tf32_of(af[q] - __uint_as_float(abig[mt][q]));
                }
            }
            #pragma unroll
            for (int nt = 0; nt < NT; nt++) {
                const int col = wx * WN + nt * 8 + grp;
                float4 qd = Bp[(ks * BN + col) * 4 + ctg];
                uint32_t bb0 = __float_as_uint(qd.x);
                uint32_t bb1 = __float_as_uint(qd.y);
                uint32_t br0 = __float_as_uint(qd.z);
                uint32_t br1 = __float_as_uint(qd.w);
                #pragma unroll
                for (int mt = 0; mt < MT; mt++) {
                    mma_tf32(acc[mt][nt], abig[mt], bb0, bb1);
                    mma_tf32(acc[mt][nt], abig[mt], br0, br1);
                    mma_tf32(acc[mt][nt], ares[mt], bb0, bb1);
                }
            }
        }
    };

    const int nch = K / BK;
    copy_chunk(0, 0);
    for (int ch = 0; ch < nch; ch++) {
        const int cur = ch & 1;
        if (ch + 1 < nch) { copy_chunk(ch + 1, cur ^ 1); CP_WAIT1(); }
        else              { CP_WAIT0(); }
        __syncthreads();
        compute(cur);
        __syncthreads();
    }

    #pragma unroll
    for (int mt = 0; mt < MT; mt++) {
        const int r0 = m0 + wy * (BM / 4) + mt * 16 + grp;
        #pragma unroll
        for (int nt = 0; nt < NT; nt++) {
            const int col = n0 + wx * WN + nt * 8 + 2 * ctg;
            float b0 = bias[col], b1 = bias[col + 1];
            float2 v0, v1;
            v0.x = acc[mt][nt][0] + b0; v0.y = acc[mt][nt][1] + b1;
            v1.x = acc[mt][nt][2] + b0; v1.y = acc[mt][nt][3] + b1;
            if (RELU) {
                v0.x = fmaxf(v0.x, 0.0f); v0.y = fmaxf(v0.y, 0.0f);
                v1.x = fmaxf(v1.x, 0.0f); v1.y = fmaxf(v1.y, 0.0f);
            }
            *(float2*)&C[(size_t)r0 * N + col] = v0;
            *(float2*)&C[(size_t)(r0 + 8) * N + col] = v1;

            if (PACKQ) {
                // Assemble packed fragment quads: lane ctg pairs with ctg^2
                // (cols c and c+4). Assigned c' = ((ctg&1)<<1)|(ctg>>1).
                float rx0 = __shfl_xor_sync(0xffffffffu, v0.x, 2);
                float ry0 = __shfl_xor_sync(0xffffffffu, v0.y, 2);
                float rx1 = __shfl_xor_sync(0xffffffffu, v1.x, 2);
                float ry1 = __shfl_xor_sync(0xffffffffu, v1.y, 2);
                float kx0, ky0, kx1, ky1;
                if (ctg < 2) { kx0 = v0.x; ky0 = rx0; kx1 = v1.x; ky1 = rx1; }
                else         { kx0 = ry0;  ky0 = v0.y; kx1 = ry1; ky1 = v1.y; }
                int cpa = ((ctg & 1) << 1) | (ctg >> 1);
                int kg8 = (n0 + wx * WN + nt * 8) >> 3;
                int ks  = kg8 & 3;
                int slot = (cpa + (r0 >> 1) + ks) & 3;   // same for r0+8
                float4 q0, q1;
                q0.x = tf32f(kx0); q0.y = tf32f(ky0);
                q0.z = tf32f(kx0 - q0.x); q0.w = tf32f(ky0 - q0.y);
                q1.x = tf32f(kx1); q1.y = tf32f(ky1);
                q1.z = tf32f(kx1 - q1.x); q1.w = tf32f(ky1 - q1.y);
                Cp[(size_t)r0 * (N / 2) + kg8 * 4 + slot] = q0;
                Cp[(size_t)(r0 + 8) * (N / 2) + kg8 * 4 + slot] = q1;
            }
        }
    }
}

// ===========================================================================
// VQ kernel: packed-quad Z (from enc2 epilogue) + packed-quad codebook.
// Mainloop = pure LDS.128 + HMMA + compare/select (argmax accumulator-init).
// Smem: Zp 2560 f4 | CbP 2x2048 f4 | CNs 256 fl | lsum 128 fl = 108032 B
// ===========================================================================
#define VQ_SMEM_BYTES ((2560 + 4096) * 16 + (256 + 128) * 4)

__global__ __launch_bounds__(256, 2) void vq_kernel(
    const float* __restrict__ ze,
    const float4* __restrict__ zep,
    const float* __restrict__ cb,
    const float4* __restrict__ cbp,
    const float* __restrict__ cnh,
    float* __restrict__ zq,
    float* __restrict__ idxf,
    float* __restrict__ losspart,
    float* __restrict__ lossout)
{
    extern __shared__ __align__(16) float4 sm4[];
    float4* Zp = sm4;                                   // [128][20] (16 used + pad)
    float4* CbP[2] = { sm4 + 2560, sm4 + 2560 + 2048 };
    float* tail = (float*)(sm4 + 2560 + 4096);
    float* CNs  = tail;                                 // [2][128] (cnh)
    float* lsum = tail + 256;

    const int tid = threadIdx.x;
    const int wid = tid >> 5;
    const int lane = tid & 31;
    const int grp = lane >> 2;
    const int ctg = lane & 3;
    const int wy  = wid & 3;
    const int wx  = wid >> 2;
    const int g    = blockIdx.y;
    const int row0 = blockIdx.x * 128;

    const float*  cgb  = cb  + (size_t)g * KCB * GD;
    const float4* cbpg = cbp + (size_t)g * 16384;
    const float*  cng  = cnh + g * KCB;

    auto copyC = [&](int ch, int buf) {
        uint32_t bs = smem_u32(CbP[buf]);
        #pragma unroll
        for (int u = 0; u < 8; u++) {
            int f = tid + u * 256;
            int kgl = f >> 9;
            int rem = f & 511;
            int cwl = rem >> 2, c = rem & 3;
            cp_async16(bs + (uint32_t)f * 16,
                       &cbpg[((size_t)kgl * 1024 + ch * 128 + cwl) * 4 + c]);
        }
        if (tid < 32)
            cp_async16(smem_u32(CNs + buf * 128) + tid * 16, cng + ch * 128 + tid * 4);
    };

    {
        uint32_t zs = smem_u32(Zp);
        #pragma unroll
        for (int u = 0; u < 8; u++) {        // 2048 f4: 128 rows x 16
            int f = tid + u * 256;
            int r = f >> 4, j = f & 15;
            cp_async16(zs + (uint32_t)(r * 20 + j) * 16,
                       &zep[(size_t)(row0 + r) * 128 + g * 16 + j]);
        }
        copyC(0, 0);
        CP_COMMIT();
        copyC(1, 1);
        CP_COMMIT();
    }
    CP_WAIT1();
    __syncthreads();

    float best[4];
    int   bidx[4];
    #pragma unroll
    for (int i = 0; i < 4; i++) { best[i] = -FLT_MAX; bidx[i] = 0; }

    int buf = 0;
    for (int ch = 0; ch < 8; ch++) {
        const float* CNc = CNs + buf * 128;
        float acc[2][8][4];
        #pragma unroll
        for (int nt = 0; nt < 8; nt++) {
            const int cbase = wx * 64 + nt * 8 + 2 * ctg;
            float c0 = CNc[cbase], c1 = CNc[cbase + 1];
            #pragma unroll
            for (int mt = 0; mt < 2; mt++) {
                acc[mt][nt][0] = c0; acc[mt][nt][1] = c1;
                acc[mt][nt][2] = c0; acc[mt][nt][3] = c1;
            }
        }

        const float4* Bp = CbP[buf];
        #pragma unroll
        for (int ks = 0; ks < 4; ks++) {
            uint32_t abig[2][4], ares[2][4];
            #pragma unroll
            for (int mt = 0; mt < 2; mt++) {
                const int r0 = wy * 32 + mt * 16 + grp;
                const int slot = (ctg + (r0 >> 1) + ks) & 3;
                float4 q0 = Zp[r0 * 20 + ks * 4 + slot];
                float4 q1 = Zp[(r0 + 8) * 20 + ks * 4 + slot];
                abig[mt][0] = __float_as_uint(q0.x);
                abig[mt][1] = __float_as_uint(q1.x);
                abig[mt][2] = __float_as_uint(q0.y);
                abig[mt][3] = __float_as_uint(q1.y);
                ares[mt][0] = __float_as_uint(q0.z);
                ares[mt][1] = __float_as_uint(q1.z);
                ares[mt][2] = __float_as_uint(q0.w);
                ares[mt][3] = __float_as_uint(q1.w);
            }
            #pragma unroll
            for (int nt = 0; nt < 8; nt++) {
                const int col = wx * 64 + nt * 8 + grp;
                float4 qd = Bp[(ks * 128 + col) * 4 + ctg];
                uint32_t cb0 = __float_as_uint(qd.x);
                uint32_t cb1 = __float_as_uint(qd.y);
                uint32_t cr0 = __float_as_uint(qd.z);
                uint32_t cr1 = __float_as_uint(qd.w);
                #pragma unroll
                for (int mt = 0; mt < 2; mt++) {
                    mma_tf32(acc[mt][nt], abig[mt], cb0, cb1);
                    mma_tf32(acc[mt][nt], abig[mt], cr0, cr1);
                    mma_tf32(acc[mt][nt], ares[mt], cb0, cb1);
                }
            }
        }

        // argmax epilogue (strict > keeps lowest index)
        #pragma unroll
        for (int nt = 0; nt < 8; nt++) {
            const int cbase = wx * 64 + nt * 8 + 2 * ctg;
            int k0 = ch * 128 + cbase;
            #pragma unroll
            for (int mt = 0; mt < 2; mt++) {
                float v00 = acc[mt][nt][0], v01 = acc[mt][nt][1];
                float v10 = acc[mt][nt][2], v11 = acc[mt][nt][3];
                if (v00 > best[mt * 2])     { best[mt * 2] = v00;     bidx[mt * 2] = k0; }
                if (v01 > best[mt * 2])     { best[mt * 2] = v01;     bidx[mt * 2] = k0 + 1; }
                if (v10 > best[mt * 2 + 1]) { best[mt * 2 + 1] = v10; bidx[mt * 2 + 1] = k0; }
                if (v11 > best[mt * 2 + 1]) { best[mt * 2 + 1] = v11; bidx[mt * 2 + 1] = k0 + 1; }
            }
        }
        __syncthreads();
        if (ch + 2 < 8) { copyC(ch + 2, buf); }
        if (ch + 1 < 8) {
            if (ch + 2 < 8) CP_WAIT1(); else CP_WAIT0();
            __syncthreads();
        }
        buf ^= 1;
    }

    // Cross-thread argmax reduction (8 slots/row; tie -> lowest idx)
    float* redV = (float*)CbP[0];
    int*   redI = (int*)((float*)CbP[0] + 1024);
    #pragma unroll
    for (int s = 0; s < 4; s++) {
        int row = wy * 32 + (s >> 1) * 16 + (s & 1) * 8 + grp;
        redV[row * 8 + wx * 4 + ctg] = best[s];
        redI[row * 8 + wx * 4 + ctg] = bidx[s];
    }
    __syncthreads();

    if (tid < 128) {
        int   r  = tid;
        float bv = redV[r * 8];
        int   bi = redI[r * 8];
        #pragma unroll
        for (int t = 1; t < 8; t++) {
            float v  = redV[r * 8 + t];
            int   i2 = redI[r * 8 + t];
            if (v > bv || (v == bv && i2 < bi)) { bv = v; bi = i2; }
        }
        int grow = row0 + r;
        idxf[(size_t)grow * GRP + g] = (float)bi;

        const float* zrow = ze + (size_t)grow * LATENT + g * GD;   // exact fp32
        const float* cw   = cgb + (size_t)bi * GD;
        float*       zqo  = zq + (size_t)grow * LATENT + g * GD;
        float diff2 = 0.0f;
        #pragma unroll
        for (int dq = 0; dq < 8; dq++) {
            float4 c4 = *(const float4*)&cw[dq * 4];
            float4 z4 = *(const float4*)&zrow[dq * 4];
            float d0 = c4.x - z4.x, d1 = c4.y - z4.y;
            float d2 = c4.z - z4.z, d3 = c4.w - z4.w;
            diff2 = fmaf(d0, d0, diff2);
            diff2 = fmaf(d1, d1, diff2);
            diff2 = fmaf(d2, d2, diff2);
            diff2 = fmaf(d3, d3, diff2);
            *(float4*)&zqo[dq * 4] = c4;
        }
        lsum[r] = diff2;
    }
    __syncthreads();

    __shared__ bool is_last;
    if (tid == 0) {
        float s = 0.0f;
        for (int r = 0; r < 128; r++) s += lsum[r];
        losspart[blockIdx.y * gridDim.x + blockIdx.x] = s;
        __threadfence();
        unsigned int t = atomicAdd(&g_cnt, 1u);
        is_last = (t == (unsigned int)(gridDim.x * gridDim.y - 1));
    }
    __syncthreads();

    if (is_last) {
        int npart = gridDim.x * gridDim.y;
        float v = 0.0f;
        for (int i = tid; i < npart; i += 256) v += losspart[i];
        redV[tid] = v;
        __syncthreads();
        for (int off = 128; off > 0; off >>= 1) {
            if (tid < off) redV[tid] += redV[tid + off];
            __syncthreads();
        }
        if (tid == 0) {
            lossout[0] = redV[0] * (1.0f / 1024000.0f);
            g_cnt = 0;
        }
    }
}

// ===========================================================================
extern "C" void kernel_launch(void* const* d_in, const int* in_sizes, int n_in,
                              void* d_out, int out_size)
{
    const float* bands = (const float*)d_in[0];
    const float* ew1   = (const float*)d_in[1];
    const float* eb1   = (const float*)d_in[2];
    const float* ew2   = (const float*)d_in[3];
    const float* eb2   = (const float*)d_in[4];
    const float* cb    = (const float*)d_in[5];
    const float* dw1   = (const float*)d_in[6];
    const float* db1   = (const float*)d_in[7];
    const float* dw2   = (const float*)d_in[8];
    const float* db2   = (const float*)d_in[9];

    float* out  = (float*)d_out;
    float* bhat = out;
    float* ze   = bhat + 1024000;
    float* zq   = ze   + 4096000;
    float* idxf = zq   + 4096000;
    float* loss = idxf + 128000;

    float *hid, *lpart, *cnh;
    float4 *wtp, *cbp, *zep;
    cudaGetSymbolAddress((void**)&hid,   g_hidden);
    cudaGetSymbolAddress((void**)&lpart, g_loss_part);
    cudaGetSymbolAddress((void**)&wtp,   g_wtp);
    cudaGetSymbolAddress((void**)&cbp,   g_cbp);
    cudaGetSymbolAddress((void**)&cnh,   g_cnh);
    cudaGetSymbolAddress((void**)&zep,   g_zep);

    const float4* e1p = wtp;
    const float4* e2p = wtp + 16384;
    const float4* d1p = wtp + 81920;
    const float4* d2p = wtp + 147456;

    const int SM128 = (2 * 128 * 36 + 2 * 4 * 128 * 16) * 4;   // 102400
    const int SM64  = (2 * 64 * 36 + 2 * 4 * 64 * 16) * 4;     // 51200
    cudaFuncSetAttribute((const void*)tgemm<128, 128, true,  false>,
                         cudaFuncAttributeMaxDynamicSharedMemorySize, SM128);
    cudaFuncSetAttribute((const void*)tgemm<128, 128, false, true >,
                         cudaFuncAttributeMaxDynamicSharedMemorySize, SM128);
    cudaFuncSetAttribute((const void*)tgemm<64, 64, false, false>,
                         cudaFuncAttributeMaxDynamicSharedMemorySize, SM64);
    cudaFuncSetAttribute((const void*)vq_kernel,
                         cudaFuncAttributeMaxDynamicSharedMemorySize, VQ_SMEM_BYTES);

    // Fused packed split (single launch)
    split_fused<<<672, 256>>>(ew1, ew2, dw1, dw2, cb, wtp, cbp, cnh);

    // Encoder (enc2 additionally emits packed z_e for VQ)
    tgemm<128, 128, true,  false><<<dim3(HIDDEN / 128, NROWS / 128), 256, SM128>>>(
        bands, e1p, eb1, hid, nullptr, NROWS, HIDDEN, NBANDS);
    tgemm<128, 128, false, true ><<<dim3(LATENT / 128, NROWS / 128), 256, SM128>>>(
        hid, e2p, eb2, ze, zep, NROWS, LATENT, HIDDEN);

    // Vector quantization (packed Z + packed codebook, argmax accumulator-init)
    vq_kernel<<<dim3(NROWS / 128, GRP), 256, VQ_SMEM_BYTES>>>(
        ze, zep, cb, cbp, cnh, zq, idxf, lpart, loss);

    // Decoder
    tgemm<128, 128, true,  false><<<dim3(HIDDEN / 128, NROWS / 128), 256, SM128>>>(
        zq, d1p, db1, hid, nullptr, NROWS, HIDDEN, LATENT);
    tgemm<64, 64, false, false><<<dim3(NBANDS / 64, NROWS / 64), 256, SM64>>>(
        hid, d2p, db2, bhat, nullptr, NROWS, NBANDS, HIDDEN);
}

// round 15
// speedup vs baseline: 1.1595x; 1.1595x over previous
#include <cuda_runtime.h>
#include <cstdint>
#include <cfloat>

#define NROWS   16000
#define NBANDS  64
#define HIDDEN  512
#define LATENT  256
#define GRP     8
#define GD      32
#define KCB     1024

__device__ float g_hidden[NROWS * HIDDEN];
__device__ float g_loss_part[1024];
__device__ unsigned int g_cnt = 0;

// Packed fragment-quad weights: [kg][n][ctg] float4 = (b_k, b_k+4, r_k, r_k+4)
__device__ float4 g_wtp[163840];
// Packed codebook: [g][kg(4)][cw(1024)][ctg(4)] float4
__device__ float4 g_cbp[GRP * 16384];
__device__ float  g_cnh[GRP * KCB];          // -0.5 * ||c||^2 (exact scale)

// ===========================================================================
// Helpers
// ===========================================================================
__device__ __forceinline__ uint32_t smem_u32(const void* p) {
    uint32_t a;
    asm("{ .reg .u64 t; cvta.to.shared.u64 t, %1; cvt.u32.u64 %0, t; }" : "=r"(a) : "l"(p));
    return a;
}
__device__ __forceinline__ uint32_t tf32_of(float x) {
    uint32_t r;
    asm("cvt.rna.tf32.f32 %0, %1;" : "=r"(r) : "f"(x));
    return r;
}
__device__ __forceinline__ float tf32f(float x) {
    return __uint_as_float(tf32_of(x));
}
__device__ __forceinline__ void cp_async16(uint32_t saddr, const void* g) {
    asm volatile("cp.async.cg.shared.global [%0], [%1], 16;" :: "r"(saddr), "l"(g));
}
#define CP_COMMIT() asm volatile("cp.async.commit_group;" ::: "memory")
#define CP_WAIT0()  asm volatile("cp.async.wait_group 0;" ::: "memory")
#define CP_WAIT1()  asm volatile("cp.async.wait_group 1;" ::: "memory")

__device__ __forceinline__ void mma_tf32(float* c, const uint32_t* a, uint32_t b0, uint32_t b1) {
    asm volatile(
        "mma.sync.aligned.m16n8k8.row.col.f32.tf32.tf32.f32 "
        "{%0,%1,%2,%3}, {%4,%5,%6,%7}, {%8,%9}, {%0,%1,%2,%3};"
        : "+f"(c[0]), "+f"(c[1]), "+f"(c[2]), "+f"(c[3])
        : "r"(a[0]), "r"(a[1]), "r"(a[2]), "r"(a[3]), "r"(b0), "r"(b1));
}

// ===========================================================================
// Single fused split kernel: blocks [0,640) pack weights, [640,672) codebook.
// ===========================================================================
__global__ void split_fused(const float* __restrict__ ew1, const float* __restrict__ ew2,
                            const float* __restrict__ dw1, const float* __restrict__ dw2,
                            const float* __restrict__ cb,
                            float4* __restrict__ wtp, float4* __restrict__ cbp,
                            float* __restrict__ cnh)
{
    if (blockIdx.x < 640) {
        int i = blockIdx.x * 256 + threadIdx.x;
        const float* w; int N, off;
        if      (i < 16384)  { w = ew1; N = 512; off = i; }
        else if (i < 81920)  { w = ew2; N = 256; off = i - 16384; }
        else if (i < 147456) { w = dw1; N = 512; off = i - 81920; }
        else                 { w = dw2; N = 64;  off = i - 147456; }
        int ctg = off & 3;
        int rem = off >> 2;
        int n = rem % N, kg = rem / N;
        float x0 = w[(size_t)(kg * 8 + ctg) * N + n];
        float x1 = w[(size_t)(kg * 8 + 4 + ctg) * N + n];
        float b0 = tf32f(x0);
        float b1 = tf32f(x1);
        float r0 = tf32f(x0 - b0);
        float r1 = tf32f(x1 - b1);
        wtp[i] = make_float4(b0, b1, r0, r1);
    } else {
        int row = (blockIdx.x - 640) * 256 + threadIdx.x;
        if (row >= GRP * KCB) return;
        int g = row >> 10, cw = row & 1023;
        const float* src = cb + (size_t)row * GD;
        float bg[GD], rs[GD], s = 0.0f;
        #pragma unroll
        for (int d = 0; d < GD; d++) {
            float x = src[d];
            bg[d] = tf32f(x);
            rs[d] = tf32f(x - bg[d]);
            s = fmaf(x, x, s);
        }
        cnh[row] = -0.5f * s;
        float4* dst = cbp + (size_t)g * 16384;
        #pragma unroll
        for (int kg = 0; kg < 4; kg++)
            #pragma unroll
            for (int ctg = 0; ctg < 4; ctg++)
                dst[(kg * 1024 + cw) * 4 + ctg] =
                    make_float4(bg[kg * 8 + ctg], bg[kg * 8 + 4 + ctg],
                                rs[kg * 8 + ctg], rs[kg * 8 + 4 + ctg]);
    }
}

// ===========================================================================
// Tensor GEMM, packed-quad B, in-loop A conversion.
// FULL=true: 3xtf32 (encoder — argmin-critical accuracy).
// FULL=false: 2xtf32, drops res(A)*big(B) MMA and A-residual prep (decoder —
//             only affects bands_hat, negligible in output norm).
// ===========================================================================
template<int BM, int BN, bool RELU, bool FULL>
__global__ __launch_bounds__(256, 2) void tgemm(
    const float* __restrict__ A,
    const float4* __restrict__ Wp,
    const float* __restrict__ bias, float* __restrict__ C,
    int M, int N, int K)
{
    constexpr int BK = 32;
    constexpr int ASTR = 36;
    constexpr int WN = BN / 2, NT = WN / 8;
    constexpr int MT = BM / 64;
    constexpr int ASZ = BM * ASTR;
    constexpr int BSZ4 = 4 * BN * 4;
    constexpr int A_Q = BM / 32;
    constexpr int B_Q = BN / 16;

    extern __shared__ __align__(16) float sm[];
    float*  AsBuf[2] = { sm, sm + ASZ };
    float4* BpBuf[2] = { (float4*)(sm + 2 * ASZ), (float4*)(sm + 2 * ASZ) + BSZ4 };

    const int tid = threadIdx.x;
    const int wid = tid >> 5;
    const int lane = tid & 31;
    const int grp = lane >> 2;
    const int ctg = lane & 3;
    const int wy  = wid & 3;
    const int wx  = wid >> 2;
    const int m0  = blockIdx.y * BM;
    const int n0  = blockIdx.x * BN;

    float acc[MT][NT][4];
    #pragma unroll
    for (int mt = 0; mt < MT; mt++)
        #pragma unroll
        for (int nt = 0; nt < NT; nt++)
            #pragma unroll
            for (int q = 0; q < 4; q++) acc[mt][nt][q] = 0.0f;

    auto copy_chunk = [&](int ch, int buf) {
        const int k0 = ch * BK;
        const int kg0 = ch * 4;
        uint32_t as = smem_u32(AsBuf[buf]);
        uint32_t bs = smem_u32(BpBuf[buf]);
        #pragma unroll
        for (int u = 0; u < A_Q; u++) {
            int f = tid + u * 256;
            int r = f >> 3, q = f & 7;
            cp_async16(as + (uint32_t)(r * ASTR + q * 4) * 4,
                       &A[(size_t)(m0 + r) * K + k0 + q * 4]);
        }
        #pragma unroll
        for (int u = 0; u < B_Q; u++) {
            int f = tid + u * 256;
            int kgl = f / (BN * 4);
            int rem = f % (BN * 4);
            int nl = rem >> 2, c = rem & 3;
            cp_async16(bs + (uint32_t)f * 16,
                       &Wp[((size_t)(kg0 + kgl) * N + n0 + nl) * 4 + c]);
        }
        CP_COMMIT();
    };

    auto compute = [&](int buf) {
        const float*  As = AsBuf[buf];
        const float4* Bp = BpBuf[buf];
        #pragma unroll
        for (int ks = 0; ks < 4; ks++) {
            const int k8 = ks * 8;
            uint32_t abig[MT][4], ares[MT][4];
            #pragma unroll
            for (int mt = 0; mt < MT; mt++) {
                const int rb = wy * (BM / 4) + mt * 16;
                float af[4];
                af[0] = As[(rb + grp) * ASTR + k8 + ctg];
                af[1] = As[(rb + 8 + grp) * ASTR + k8 + ctg];
                af[2] = As[(rb + grp) * ASTR + k8 + 4 + ctg];
                af[3] = As[(rb + 8 + grp) * ASTR + k8 + 4 + ctg];
                #pragma unroll
                for (int q = 0; q < 4; q++) {
                    abig[mt][q] = tf32_of(af[q]);
                    if (FULL)
                        ares[mt][q] = tf32_of(af[q] - __uint_as_float(abig[mt][q]));
                }
            }
            #pragma unroll
            for (int nt = 0; nt < NT; nt++) {
                const int col = wx * WN + nt * 8 + grp;
                float4 qd = Bp[(ks * BN + col) * 4 + ctg];
                uint32_t bb0 = __float_as_uint(qd.x);
                uint32_t bb1 = __float_as_uint(qd.y);
                uint32_t br0 = __float_as_uint(qd.z);
                uint32_t br1 = __float_as_uint(qd.w);
                #pragma unroll
                for (int mt = 0; mt < MT; mt++) {
                    mma_tf32(acc[mt][nt], abig[mt], bb0, bb1);
                    mma_tf32(acc[mt][nt], abig[mt], br0, br1);
                    if (FULL)
                        mma_tf32(acc[mt][nt], ares[mt], bb0, bb1);
                }
            }
        }
    };

    const int nch = K / BK;
    copy_chunk(0, 0);
    for (int ch = 0; ch < nch; ch++) {
        const int cur = ch & 1;
        if (ch + 1 < nch) { copy_chunk(ch + 1, cur ^ 1); CP_WAIT1(); }
        else              { CP_WAIT0(); }
        __syncthreads();
        compute(cur);
        __syncthreads();
    }

    #pragma unroll
    for (int mt = 0; mt < MT; mt++) {
        const int r0 = m0 + wy * (BM / 4) + mt * 16 + grp;
        #pragma unroll
        for (int nt = 0; nt < NT; nt++) {
            const int col = n0 + wx * WN + nt * 8 + 2 * ctg;
            float b0 = bias[col], b1 = bias[col + 1];
            float2 v0, v1;
            v0.x = acc[mt][nt][0] + b0; v0.y = acc[mt][nt][1] + b1;
            v1.x = acc[mt][nt][2] + b0; v1.y = acc[mt][nt][3] + b1;
            if (RELU) {
                v0.x = fmaxf(v0.x, 0.0f); v0.y = fmaxf(v0.y, 0.0f);
                v1.x = fmaxf(v1.x, 0.0f); v1.y = fmaxf(v1.y, 0.0f);
            }
            *(float2*)&C[(size_t)r0 * N + col] = v0;
            *(float2*)&C[(size_t)(r0 + 8) * N + col] = v1;
        }
    }
}

// ===========================================================================
// VQ kernel (round-13, known good 147.5us): 128-row tiles, packed-quad
// codebook, in-loop Z conversion, argmax accumulator-init, fused loss.
// ===========================================================================
#define VQ_SMEM_FLOATS 21376

__global__ __launch_bounds__(256, 2) void vq_kernel(
    const float* __restrict__ ze,
    const float* __restrict__ cb,
    const float4* __restrict__ cbp,
    const float* __restrict__ cnh,
    float* __restrict__ zq,
    float* __restrict__ idxf,
    float* __restrict__ losspart,
    float* __restrict__ lossout)
{
    extern __shared__ __align__(16) float sm[];
    float*  Zs = sm;                                       // [128][36]
    float4* CbP[2] = { (float4*)(sm + 4608), (float4*)(sm + 4608) + 2048 };
    float* CNs  = sm + 4608 + 16384;                       // [2][128] (cnh)
    float* lsum = CNs + 256;

    const int tid = threadIdx.x;
    const int wid = tid >> 5;
    const int lane = tid & 31;
    const int grp = lane >> 2;
    const int ctg = lane & 3;
    const int wy  = wid & 3;
    const int wx  = wid >> 2;
    const int g    = blockIdx.y;
    const int row0 = blockIdx.x * 128;

    const float*  zbase = ze  + (size_t)row0 * LATENT + g * GD;
    const float*  cgb   = cb  + (size_t)g * KCB * GD;
    const float4* cbpg  = cbp + (size_t)g * 16384;
    const float*  cng   = cnh + g * KCB;

    auto copyC = [&](int ch, int buf) {
        uint32_t bs = smem_u32(CbP[buf]);
        #pragma unroll
        for (int u = 0; u < 8; u++) {
            int f = tid + u * 256;
            int kgl = f >> 9;
            int rem = f & 511;
            int cwl = rem >> 2, c = rem & 3;
            cp_async16(bs + (uint32_t)f * 16,
                       &cbpg[((size_t)kgl * 1024 + ch * 128 + cwl) * 4 + c]);
        }
        if (tid < 32)
            cp_async16(smem_u32(CNs + buf * 128) + tid * 16, cng + ch * 128 + tid * 4);
    };

    {
        uint32_t zs = smem_u32(Zs);
        #pragma unroll
        for (int u = 0; u < 4; u++) {
            int f = tid + u * 256;
            int r = f >> 3, q = f & 7;
            cp_async16(zs + (uint32_t)(r * 36 + q * 4) * 4,
                       zbase + (size_t)r * LATENT + q * 4);
        }
        copyC(0, 0);
        CP_COMMIT();
        copyC(1, 1);
        CP_COMMIT();
    }
    CP_WAIT1();
    __syncthreads();

    float best[4];
    int   bidx[4];
    #pragma unroll
    for (int i = 0; i < 4; i++) { best[i] = -FLT_MAX; bidx[i] = 0; }

    int buf = 0;
    for (int ch = 0; ch < 8; ch++) {
        const float* CNc = CNs + buf * 128;
        float acc[2][8][4];
        #pragma unroll
        for (int nt = 0; nt < 8; nt++) {
            const int cbase = wx * 64 + nt * 8 + 2 * ctg;
            float c0 = CNc[cbase], c1 = CNc[cbase + 1];
            #pragma unroll
            for (int mt = 0; mt < 2; mt++) {
                acc[mt][nt][0] = c0; acc[mt][nt][1] = c1;
                acc[mt][nt][2] = c0; acc[mt][nt][3] = c1;
            }
        }

        const float4* Bp = CbP[buf];
        #pragma unroll
        for (int ks = 0; ks < 4; ks++) {
            const int k8 = ks * 8;
            uint32_t abig[2][4], ares[2][4];
            #pragma unroll
            for (int mt = 0; mt < 2; mt++) {
                const int rb = wy * 32 + mt * 16;
                float af[4];
                af[0] = Zs[(rb + grp) * 36 + k8 + ctg];
                af[1] = Zs[(rb + 8 + grp) * 36 + k8 + ctg];
                af[2] = Zs[(rb + grp) * 36 + k8 + 4 + ctg];
                af[3] = Zs[(rb + 8 + grp) * 36 + k8 + 4 + ctg];
                #pragma unroll
                for (int q = 0; q < 4; q++) {
                    abig[mt][q] = tf32_of(af[q]);
                    ares[mt][q] = tf32_of(af[q] - __uint_as_float(abig[mt][q]));
                }
            }
            #pragma unroll
            for (int nt = 0; nt < 8; nt++) {
                const int col = wx * 64 + nt * 8 + grp;
                float4 qd = Bp[(ks * 128 + col) * 4 + ctg];
                uint32_t cb0 = __float_as_uint(qd.x);
                uint32_t cb1 = __float_as_uint(qd.y);
                uint32_t cr0 = __float_as_uint(qd.z);
                uint32_t cr1 = __float_as_uint(qd.w);
                #pragma unroll
                for (int mt = 0; mt < 2; mt++) {
                    mma_tf32(acc[mt][nt], abig[mt], cb0, cb1);
                    mma_tf32(acc[mt][nt], abig[mt], cr0, cr1);
                    mma_tf32(acc[mt][nt], ares[mt], cb0, cb1);
                }
            }
        }

        // argmax epilogue (strict > keeps lowest index)
        #pragma unroll
        for (int nt = 0; nt < 8; nt++) {
            const int cbase = wx * 64 + nt * 8 + 2 * ctg;
            int k0 = ch * 128 + cbase;
            #pragma unroll
            for (int mt = 0; mt < 2; mt++) {
                float v00 = acc[mt][nt][0], v01 = acc[mt][nt][1];
                float v10 = acc[mt][nt][2], v11 = acc[mt][nt][3];
                if (v00 > best[mt * 2])     { best[mt * 2] = v00;     bidx[mt * 2] = k0; }
                if (v01 > best[mt * 2])     { best[mt * 2] = v01;     bidx[mt * 2] = k0 + 1; }
                if (v10 > best[mt * 2 + 1]) { best[mt * 2 + 1] = v10; bidx[mt * 2 + 1] = k0; }
                if (v11 > best[mt * 2 + 1]) { best[mt * 2 + 1] = v11; bidx[mt * 2 + 1] = k0 + 1; }
            }
        }
        __syncthreads();
        if (ch + 2 < 8) { copyC(ch + 2, buf); }
        if (ch + 1 < 8) {
            if (ch + 2 < 8) CP_WAIT1(); else CP_WAIT0();
            __syncthreads();
        }
        buf ^= 1;
    }

    // Cross-thread argmax reduction (8 slots/row; tie -> lowest idx)
    float* redV = (float*)CbP[0];
    int*   redI = (int*)((float*)CbP[0] + 1024);
    #pragma unroll
    for (int s = 0; s < 4; s++) {
        int row = wy * 32 + (s >> 1) * 16 + (s & 1) * 8 + grp;
        redV[row * 8 + wx * 4 + ctg] = best[s];
        redI[row * 8 + wx * 4 + ctg] = bidx[s];
    }
    __syncthreads();

    if (tid < 128) {
        int   r  = tid;
        float bv = redV[r * 8];
        int   bi = redI[r * 8];
        #pragma unroll
        for (int t = 1; t < 8; t++) {
            float v  = redV[r * 8 + t];
            int   i2 = redI[r * 8 + t];
            if (v > bv || (v == bv && i2 < bi)) { bv = v; bi = i2; }
        }
        int grow = row0 + r;
        idxf[(size_t)grow * GRP + g] = (float)bi;

        const float* cw  = cgb + (size_t)bi * GD;
        float*       zqo = zq + (size_t)grow * LATENT + g * GD;
        float diff2 = 0.0f;
        #pragma unroll
        for (int dq = 0; dq < 8; dq++) {
            float4 c4 = *(const float4*)&cw[dq * 4];
            float d0 = c4.x - Zs[r * 36 + dq * 4 + 0];
            float d1 = c4.y - Zs[r * 36 + dq * 4 + 1];
            float d2 = c4.z - Zs[r * 36 + dq * 4 + 2];
            float d3 = c4.w - Zs[r * 36 + dq * 4 + 3];
            diff2 = fmaf(d0, d0, diff2);
            diff2 = fmaf(d1, d1, diff2);
            diff2 = fmaf(d2, d2, diff2);
            diff2 = fmaf(d3, d3, diff2);
            *(float4*)&zqo[dq * 4] = c4;
        }
        lsum[r] = diff2;
    }
    __syncthreads();

    __shared__ bool is_last;
    if (tid == 0) {
        float s = 0.0f;
        for (int r = 0; r < 128; r++) s += lsum[r];
        losspart[blockIdx.y * gridDim.x + blockIdx.x] = s;
        __threadfence();
        unsigned int t = atomicAdd(&g_cnt, 1u);
        is_last = (t == (unsigned int)(gridDim.x * gridDim.y - 1));
    }
    __syncthreads();

    if (is_last) {
        int npart = gridDim.x * gridDim.y;
        float v = 0.0f;
        for (int i = tid; i < npart; i += 256) v += losspart[i];
        redV[tid] = v;
        __syncthreads();
        for (int off = 128; off > 0; off >>= 1) {
            if (tid < off) redV[tid] += redV[tid + off];
            __syncthreads();
        }
        if (tid == 0) {
            lossout[0] = redV[0] * (1.0f / 1024000.0f);
            g_cnt = 0;
        }
    }
}

// ===========================================================================
extern "C" void kernel_launch(void* const* d_in, const int* in_sizes, int n_in,
                              void* d_out, int out_size)
{
    const float* bands = (const float*)d_in[0];
    const float* ew1   = (const float*)d_in[1];
    const float* eb1   = (const float*)d_in[2];
    const float* ew2   = (const float*)d_in[3];
    const float* eb2   = (const float*)d_in[4];
    const float* cb    = (const float*)d_in[5];
    const float* dw1   = (const float*)d_in[6];
    const float* db1   = (const float*)d_in[7];
    const float* dw2   = (const float*)d_in[8];
    const float* db2   = (const float*)d_in[9];

    float* out  = (float*)d_out;
    float* bhat = out;
    float* ze   = bhat + 1024000;
    float* zq   = ze   + 4096000;
    float* idxf = zq   + 4096000;
    float* loss = idxf + 128000;

    float *hid, *lpart, *cnh;
    float4 *wtp, *cbp;
    cudaGetSymbolAddress((void**)&hid,   g_hidden);
    cudaGetSymbolAddress((void**)&lpart, g_loss_part);
    cudaGetSymbolAddress((void**)&wtp,   g_wtp);
    cudaGetSymbolAddress((void**)&cbp,   g_cbp);
    cudaGetSymbolAddress((void**)&cnh,   g_cnh);

    const float4* e1p = wtp;
    const float4* e2p = wtp + 16384;
    const float4* d1p = wtp + 81920;
    const float4* d2p = wtp + 147456;

    const int SM128 = (2 * 128 * 36 + 2 * 4 * 128 * 16) * 4;   // 102400
    const int SM64  = (2 * 64 * 36 + 2 * 4 * 64 * 16) * 4;     // 51200
    cudaFuncSetAttribute((const void*)tgemm<128, 128, true,  true >,
                         cudaFuncAttributeMaxDynamicSharedMemorySize, SM128);
    cudaFuncSetAttribute((const void*)tgemm<128, 128, false, true >,
                         cudaFuncAttributeMaxDynamicSharedMemorySize, SM128);
    cudaFuncSetAttribute((const void*)tgemm<128, 128, true,  false>,
                         cudaFuncAttributeMaxDynamicSharedMemorySize, SM128);
    cudaFuncSetAttribute((const void*)tgemm<64, 64, false, false>,
                         cudaFuncAttributeMaxDynamicSharedMemorySize, SM64);
    cudaFuncSetAttribute((const void*)vq_kernel,
                         cudaFuncAttributeMaxDynamicSharedMemorySize, VQ_SMEM_FLOATS * 4);

    // Fused packed split (single launch)
    split_fused<<<672, 256>>>(ew1, ew2, dw1, dw2, cb, wtp, cbp, cnh);

    // Encoder (full 3xtf32 — feeds argmin)
    tgemm<128, 128, true,  true ><<<dim3(HIDDEN / 128, NROWS / 128), 256, SM128>>>(
        bands, e1p, eb1, hid, NROWS, HIDDEN, NBANDS);
    tgemm<128, 128, false, true ><<<dim3(LATENT / 128, NROWS / 128), 256, SM128>>>(
        hid, e2p, eb2, ze, NROWS, LATENT, HIDDEN);

    // Vector quantization (128-row tiles, argmax accumulator-init)
    vq_kernel<<<dim3(NROWS / 128, GRP), 256, VQ_SMEM_FLOATS * 4>>>(
        ze, cb, cbp, cnh, zq, idxf, lpart, loss);

    // Decoder (2xtf32 — only affects bands_hat; negligible in output norm)
    tgemm<128, 128, true,  false><<<dim3(HIDDEN / 128, NROWS / 128), 256, SM128>>>(
        zq, d1p, db1, hid, NROWS, HIDDEN, LATENT);
    tgemm<64, 64, false, false><<<dim3(NBANDS / 64, NROWS / 64), 256, SM64>>>(
        hid, d2p, db2, bhat, NROWS, NBANDS, HIDDEN);
}

// round 16
// speedup vs baseline: 1.1946x; 1.0303x over previous
#include <cuda_runtime.h>
#include <cstdint>
#include <cfloat>

#define NROWS   16000
#define NBANDS  64
#define HIDDEN  512
#define LATENT  256
#define GRP     8
#define GD      32
#define KCB     1024

__device__ float g_hidden[NROWS * HIDDEN];
__device__ float g_loss_part[1024];
__device__ unsigned int g_cnt = 0;

// Packed fragment-quad weights: [kg][n][ctg] float4 = (b_k, b_k+4, r_k, r_k+4)
__device__ float4 g_wtp[163840];
// Packed codebook: [g][kg(4)][cw(1024)][ctg(4)] float4
__device__ float4 g_cbp[GRP * 16384];
__device__ float  g_cnh[GRP * KCB];          // -0.5 * ||c||^2 (exact scale)

// ===========================================================================
// Helpers
// ===========================================================================
__device__ __forceinline__ uint32_t smem_u32(const void* p) {
    uint32_t a;
    asm("{ .reg .u64 t; cvta.to.shared.u64 t, %1; cvt.u32.u64 %0, t; }" : "=r"(a) : "l"(p));
    return a;
}
__device__ __forceinline__ uint32_t tf32_of(float x) {
    uint32_t r;
    asm("cvt.rna.tf32.f32 %0, %1;" : "=r"(r) : "f"(x));
    return r;
}
__device__ __forceinline__ float tf32f(float x) {
    return __uint_as_float(tf32_of(x));
}
__device__ __forceinline__ void cp_async16(uint32_t saddr, const void* g) {
    asm volatile("cp.async.cg.shared.global [%0], [%1], 16;" :: "r"(saddr), "l"(g));
}
#define CP_COMMIT() asm volatile("cp.async.commit_group;" ::: "memory")
#define CP_WAIT0()  asm volatile("cp.async.wait_group 0;" ::: "memory")
#define CP_WAIT1()  asm volatile("cp.async.wait_group 1;" ::: "memory")

__device__ __forceinline__ void mma_tf32(float* c, const uint32_t* a, uint32_t b0, uint32_t b1) {
    asm volatile(
        "mma.sync.aligned.m16n8k8.row.col.f32.tf32.tf32.f32 "
        "{%0,%1,%2,%3}, {%4,%5,%6,%7}, {%8,%9}, {%0,%1,%2,%3};"
        : "+f"(c[0]), "+f"(c[1]), "+f"(c[2]), "+f"(c[3])
        : "r"(a[0]), "r"(a[1]), "r"(a[2]), "r"(a[3]), "r"(b0), "r"(b1));
}

// ===========================================================================
// Single fused split kernel: blocks [0,640) pack weights, [640,672) codebook.
// ===========================================================================
__global__ void split_fused(const float* __restrict__ ew1, const float* __restrict__ ew2,
                            const float* __restrict__ dw1, const float* __restrict__ dw2,
                            const float* __restrict__ cb,
                            float4* __restrict__ wtp, float4* __restrict__ cbp,
                            float* __restrict__ cnh)
{
    if (blockIdx.x < 640) {
        int i = blockIdx.x * 256 + threadIdx.x;
        const float* w; int N, off;
        if      (i < 16384)  { w = ew1; N = 512; off = i; }
        else if (i < 81920)  { w = ew2; N = 256; off = i - 16384; }
        else if (i < 147456) { w = dw1; N = 512; off = i - 81920; }
        else                 { w = dw2; N = 64;  off = i - 147456; }
        int ctg = off & 3;
        int rem = off >> 2;
        int n = rem % N, kg = rem / N;
        float x0 = w[(size_t)(kg * 8 + ctg) * N + n];
        float x1 = w[(size_t)(kg * 8 + 4 + ctg) * N + n];
        float b0 = tf32f(x0);
        float b1 = tf32f(x1);
        float r0 = tf32f(x0 - b0);
        float r1 = tf32f(x1 - b1);
        wtp[i] = make_float4(b0, b1, r0, r1);
    } else {
        int row = (blockIdx.x - 640) * 256 + threadIdx.x;
        if (row >= GRP * KCB) return;
        int g = row >> 10, cw = row & 1023;
        const float* src = cb + (size_t)row * GD;
        float bg[GD], rs[GD], s = 0.0f;
        #pragma unroll
        for (int d = 0; d < GD; d++) {
            float x = src[d];
            bg[d] = tf32f(x);
            rs[d] = tf32f(x - bg[d]);
            s = fmaf(x, x, s);
        }
        cnh[row] = -0.5f * s;
        float4* dst = cbp + (size_t)g * 16384;
        #pragma unroll
        for (int kg = 0; kg < 4; kg++)
            #pragma unroll
            for (int ctg = 0; ctg < 4; ctg++)
                dst[(kg * 1024 + cw) * 4 + ctg] =
                    make_float4(bg[kg * 8 + ctg], bg[kg * 8 + 4 + ctg],
                                rs[kg * 8 + ctg], rs[kg * 8 + 4 + ctg]);
    }
}

// ===========================================================================
// Tensor GEMM, packed-quad B, in-loop A conversion.
// FULL=true: 3xtf32 (encoder). FULL=false: 2xtf32 (decoder only).
// ===========================================================================
template<int BM, int BN, bool RELU, bool FULL>
__global__ __launch_bounds__(256, 2) void tgemm(
    const float* __restrict__ A,
    const float4* __restrict__ Wp,
    const float* __restrict__ bias, float* __restrict__ C,
    int M, int N, int K)
{
    constexpr int BK = 32;
    constexpr int ASTR = 36;
    constexpr int WN = BN / 2, NT = WN / 8;
    constexpr int MT = BM / 64;
    constexpr int ASZ = BM * ASTR;
    constexpr int BSZ4 = 4 * BN * 4;
    constexpr int A_Q = BM / 32;
    constexpr int B_Q = BN / 16;

    extern __shared__ __align__(16) float sm[];
    float*  AsBuf[2] = { sm, sm + ASZ };
    float4* BpBuf[2] = { (float4*)(sm + 2 * ASZ), (float4*)(sm + 2 * ASZ) + BSZ4 };

    const int tid = threadIdx.x;
    const int wid = tid >> 5;
    const int lane = tid & 31;
    const int grp = lane >> 2;
    const int ctg = lane & 3;
    const int wy  = wid & 3;
    const int wx  = wid >> 2;
    const int m0  = blockIdx.y * BM;
    const int n0  = blockIdx.x * BN;

    float acc[MT][NT][4];
    #pragma unroll
    for (int mt = 0; mt < MT; mt++)
        #pragma unroll
        for (int nt = 0; nt < NT; nt++)
            #pragma unroll
            for (int q = 0; q < 4; q++) acc[mt][nt][q] = 0.0f;

    auto copy_chunk = [&](int ch, int buf) {
        const int k0 = ch * BK;
        const int kg0 = ch * 4;
        uint32_t as = smem_u32(AsBuf[buf]);
        uint32_t bs = smem_u32(BpBuf[buf]);
        #pragma unroll
        for (int u = 0; u < A_Q; u++) {
            int f = tid + u * 256;
            int r = f >> 3, q = f & 7;
            cp_async16(as + (uint32_t)(r * ASTR + q * 4) * 4,
                       &A[(size_t)(m0 + r) * K + k0 + q * 4]);
        }
        #pragma unroll
        for (int u = 0; u < B_Q; u++) {
            int f = tid + u * 256;
            int kgl = f / (BN * 4);
            int rem = f % (BN * 4);
            int nl = rem >> 2, c = rem & 3;
            cp_async16(bs + (uint32_t)f * 16,
                       &Wp[((size_t)(kg0 + kgl) * N + n0 + nl) * 4 + c]);
        }
        CP_COMMIT();
    };

    auto compute = [&](int buf) {
        const float*  As = AsBuf[buf];
        const float4* Bp = BpBuf[buf];
        #pragma unroll
        for (int ks = 0; ks < 4; ks++) {
            const int k8 = ks * 8;
            uint32_t abig[MT][4], ares[MT][4];
            #pragma unroll
            for (int mt = 0; mt < MT; mt++) {
                const int rb = wy * (BM / 4) + mt * 16;
                float af[4];
                af[0] = As[(rb + grp) * ASTR + k8 + ctg];
                af[1] = As[(rb + 8 + grp) * ASTR + k8 + ctg];
                af[2] = As[(rb + grp) * ASTR + k8 + 4 + ctg];
                af[3] = As[(rb + 8 + grp) * ASTR + k8 + 4 + ctg];
                #pragma unroll
                for (int q = 0; q < 4; q++) {
                    abig[mt][q] = tf32_of(af[q]);
                    if (FULL)
                        ares[mt][q] = tf32_of(af[q] - __uint_as_float(abig[mt][q]));
                }
            }
            #pragma unroll
            for (int nt = 0; nt < NT; nt++) {
                const int col = wx * WN + nt * 8 + grp;
                float4 qd = Bp[(ks * BN + col) * 4 + ctg];
                uint32_t bb0 = __float_as_uint(qd.x);
                uint32_t bb1 = __float_as_uint(qd.y);
                uint32_t br0 = __float_as_uint(qd.z);
                uint32_t br1 = __float_as_uint(qd.w);
                #pragma unroll
                for (int mt = 0; mt < MT; mt++) {
                    mma_tf32(acc[mt][nt], abig[mt], bb0, bb1);
                    mma_tf32(acc[mt][nt], abig[mt], br0, br1);
                    if (FULL)
                        mma_tf32(acc[mt][nt], ares[mt], bb0, bb1);
                }
            }
        }
    };

    const int nch = K / BK;
    copy_chunk(0, 0);
    for (int ch = 0; ch < nch; ch++) {
        const int cur = ch & 1;
        if (ch + 1 < nch) { copy_chunk(ch + 1, cur ^ 1); CP_WAIT1(); }
        else              { CP_WAIT0(); }
        __syncthreads();
        compute(cur);
        __syncthreads();
    }

    #pragma unroll
    for (int mt = 0; mt < MT; mt++) {
        const int r0 = m0 + wy * (BM / 4) + mt * 16 + grp;
        #pragma unroll
        for (int nt = 0; nt < NT; nt++) {
            const int col = n0 + wx * WN + nt * 8 + 2 * ctg;
            float b0 = bias[col], b1 = bias[col + 1];
            float2 v0, v1;
            v0.x = acc[mt][nt][0] + b0; v0.y = acc[mt][nt][1] + b1;
            v1.x = acc[mt][nt][2] + b0; v1.y = acc[mt][nt][3] + b1;
            if (RELU) {
                v0.x = fmaxf(v0.x, 0.0f); v0.y = fmaxf(v0.y, 0.0f);
                v1.x = fmaxf(v1.x, 0.0f); v1.y = fmaxf(v1.y, 0.0f);
            }
            *(float2*)&C[(size_t)r0 * N + col] = v0;
            *(float2*)&C[(size_t)(r0 + 8) * N + col] = v1;
        }
    }
}

// ===========================================================================
// VQ kernel: 128-row tiles, packed-quad codebook, argmax accumulator-init,
// Z fragments converted ONCE and held in registers across all 8 chunks
// (acc processed in nt-halves of 4 to fit the register budget).
// Candidate values / compare order bit-identical to round-15.
// ===========================================================================
#define VQ_SMEM_FLOATS 21376

__global__ __launch_bounds__(256, 2) void vq_kernel(
    const float* __restrict__ ze,
    const float* __restrict__ cb,
    const float4* __restrict__ cbp,
    const float* __restrict__ cnh,
    float* __restrict__ zq,
    float* __restrict__ idxf,
    float* __restrict__ losspart,
    float* __restrict__ lossout)
{
    extern __shared__ __align__(16) float sm[];
    float*  Zs = sm;                                       // [128][36]
    float4* CbP[2] = { (float4*)(sm + 4608), (float4*)(sm + 4608) + 2048 };
    float* CNs  = sm + 4608 + 16384;                       // [2][128] (cnh)
    float* lsum = CNs + 256;

    const int tid = threadIdx.x;
    const int wid = tid >> 5;
    const int lane = tid & 31;
    const int grp = lane >> 2;
    const int ctg = lane & 3;
    const int wy  = wid & 3;
    const int wx  = wid >> 2;
    const int g    = blockIdx.y;
    const int row0 = blockIdx.x * 128;

    const float*  zbase = ze  + (size_t)row0 * LATENT + g * GD;
    const float*  cgb   = cb  + (size_t)g * KCB * GD;
    const float4* cbpg  = cbp + (size_t)g * 16384;
    const float*  cng   = cnh + g * KCB;

    auto copyC = [&](int ch, int buf) {
        uint32_t bs = smem_u32(CbP[buf]);
        #pragma unroll
        for (int u = 0; u < 8; u++) {
            int f = tid + u * 256;
            int kgl = f >> 9;
            int rem = f & 511;
            int cwl = rem >> 2, c = rem & 3;
            cp_async16(bs + (uint32_t)f * 16,
                       &cbpg[((size_t)kgl * 1024 + ch * 128 + cwl) * 4 + c]);
        }
        if (tid < 32)
            cp_async16(smem_u32(CNs + buf * 128) + tid * 16, cng + ch * 128 + tid * 4);
    };

    {
        uint32_t zs = smem_u32(Zs);
        #pragma unroll
        for (int u = 0; u < 4; u++) {
            int f = tid + u * 256;
            int r = f >> 3, q = f & 7;
            cp_async16(zs + (uint32_t)(r * 36 + q * 4) * 4,
                       zbase + (size_t)r * LATENT + q * 4);
        }
        copyC(0, 0);
        CP_COMMIT();
        copyC(1, 1);
        CP_COMMIT();
    }
    CP_WAIT1();
    __syncthreads();

    // Convert Z fragments ONCE; hold across all chunks (64 regs).
    uint32_t abig[4][2][4], ares[4][2][4];
    #pragma unroll
    for (int ks = 0; ks < 4; ks++) {
        const int k8 = ks * 8;
        #pragma unroll
        for (int mt = 0; mt < 2; mt++) {
            const int rb = wy * 32 + mt * 16;
            float af[4];
            af[0] = Zs[(rb + grp) * 36 + k8 + ctg];
            af[1] = Zs[(rb + 8 + grp) * 36 + k8 + ctg];
            af[2] = Zs[(rb + grp) * 36 + k8 + 4 + ctg];
            af[3] = Zs[(rb + 8 + grp) * 36 + k8 + 4 + ctg];
            #pragma unroll
            for (int q = 0; q < 4; q++) {
                abig[ks][mt][q] = tf32_of(af[q]);
                ares[ks][mt][q] = tf32_of(af[q] - __uint_as_float(abig[ks][mt][q]));
            }
        }
    }

    float best[4];
    int   bidx[4];
    #pragma unroll
    for (int i = 0; i < 4; i++) { best[i] = -FLT_MAX; bidx[i] = 0; }

    int buf = 0;
    for (int ch = 0; ch < 8; ch++) {
        const float* CNc = CNs + buf * 128;
        const float4* Bp = CbP[buf];

        #pragma unroll
        for (int h = 0; h < 2; h++) {
            float acc[2][4][4];
            #pragma unroll
            for (int j = 0; j < 4; j++) {
                const int cbase = wx * 64 + (h * 4 + j) * 8 + 2 * ctg;
                float c0 = CNc[cbase], c1 = CNc[cbase + 1];
                #pragma unroll
                for (int mt = 0; mt < 2; mt++) {
                    acc[mt][j][0] = c0; acc[mt][j][1] = c1;
                    acc[mt][j][2] = c0; acc[mt][j][3] = c1;
                }
            }
            #pragma unroll
            for (int ks = 0; ks < 4; ks++) {
                #pragma unroll
                for (int j = 0; j < 4; j++) {
                    const int col = wx * 64 + (h * 4 + j) * 8 + grp;
                    float4 qd = Bp[(ks * 128 + col) * 4 + ctg];
                    uint32_t cb0 = __float_as_uint(qd.x);
                    uint32_t cb1 = __float_as_uint(qd.y);
                    uint32_t cr0 = __float_as_uint(qd.z);
                    uint32_t cr1 = __float_as_uint(qd.w);
                    #pragma unroll
                    for (int mt = 0; mt < 2; mt++) {
                        mma_tf32(acc[mt][j], abig[ks][mt], cb0, cb1);
                        mma_tf32(acc[mt][j], abig[ks][mt], cr0, cr1);
                        mma_tf32(acc[mt][j], ares[ks][mt], cb0, cb1);
                    }
                }
            }
            // argmax epilogue for this half (strict > keeps lowest index)
            #pragma unroll
            for (int j = 0; j < 4; j++) {
                const int cbase = wx * 64 + (h * 4 + j) * 8 + 2 * ctg;
                int k0 = ch * 128 + cbase;
                #pragma unroll
                for (int mt = 0; mt < 2; mt++) {
                    float v00 = acc[mt][j][0], v01 = acc[mt][j][1];
                    float v10 = acc[mt][j][2], v11 = acc[mt][j][3];
                    if (v00 > best[mt * 2])     { best[mt * 2] = v00;     bidx[mt * 2] = k0; }
                    if (v01 > best[mt * 2])     { best[mt * 2] = v01;     bidx[mt * 2] = k0 + 1; }
                    if (v10 > best[mt * 2 + 1]) { best[mt * 2 + 1] = v10; bidx[mt * 2 + 1] = k0; }
                    if (v11 > best[mt * 2 + 1]) { best[mt * 2 + 1] = v11; bidx[mt * 2 + 1] = k0 + 1; }
                }
            }
        }
        __syncthreads();
        if (ch + 2 < 8) { copyC(ch + 2, buf); CP_COMMIT(); }
        if (ch + 1 < 8) {
            if (ch + 2 < 8) CP_WAIT1(); else CP_WAIT0();
            __syncthreads();
        }
        buf ^= 1;
    }

    // Cross-thread argmax reduction (8 slots/row; tie -> lowest idx)
    float* redV = (float*)CbP[0];
    int*   redI = (int*)((float*)CbP[0] + 1024);
    #pragma unroll
    for (int s = 0; s < 4; s++) {
        int row = wy * 32 + (s >> 1) * 16 + (s & 1) * 8 + grp;
        redV[row * 8 + wx * 4 + ctg] = best[s];
        redI[row * 8 + wx * 4 + ctg] = bidx[s];
    }
    __syncthreads();

    if (tid < 128) {
        int   r  = tid;
        float bv = redV[r * 8];
        int   bi = redI[r * 8];
        #pragma unroll
        for (int t = 1; t < 8; t++) {
            float v  = redV[r * 8 + t];
            int   i2 = redI[r * 8 + t];
            if (v > bv || (v == bv && i2 < bi)) { bv = v; bi = i2; }
        }
        int grow = row0 + r;
        idxf[(size_t)grow * GRP + g] = (float)bi;

        const float* cw  = cgb + (size_t)bi * GD;
        float*       zqo = zq + (size_t)grow * LATENT + g * GD;
        float diff2 = 0.0f;
        #pragma unroll
        for (int dq = 0; dq < 8; dq++) {
            float4 c4 = *(const float4*)&cw[dq * 4];
            float d0 = c4.x - Zs[r * 36 + dq * 4 + 0];
            float d1 = c4.y - Zs[r * 36 + dq * 4 + 1];
            float d2 = c4.z - Zs[r * 36 + dq * 4 + 2];
            float d3 = c4.w - Zs[r * 36 + dq * 4 + 3];
            diff2 = fmaf(d0, d0, diff2);
            diff2 = fmaf(d1, d1, diff2);
            diff2 = fmaf(d2, d2, diff2);
            diff2 = fmaf(d3, d3, diff2);
            *(float4*)&zqo[dq * 4] = c4;
        }
        lsum[r] = diff2;
    }
    __syncthreads();

    __shared__ bool is_last;
    if (tid == 0) {
        float s = 0.0f;
        for (int r = 0; r < 128; r++) s += lsum[r];
        losspart[blockIdx.y * gridDim.x + blockIdx.x] = s;
        __threadfence();
        unsigned int t = atomicAdd(&g_cnt, 1u);
        is_last = (t == (unsigned int)(gridDim.x * gridDim.y - 1));
    }
    __syncthreads();

    if (is_last) {
        int npart = gridDim.x * gridDim.y;
        float v = 0.0f;
        for (int i = tid; i < npart; i += 256) v += losspart[i];
        redV[tid] = v;
        __syncthreads();
        for (int off = 128; off > 0; off >>= 1) {
            if (tid < off) redV[tid] += redV[tid + off];
            __syncthreads();
        }
        if (tid == 0) {
            lossout[0] = redV[0] * (1.0f / 1024000.0f);
            g_cnt = 0;
        }
    }
}

// ===========================================================================
extern "C" void kernel_launch(void* const* d_in, const int* in_sizes, int n_in,
                              void* d_out, int out_size)
{
    const float* bands = (const float*)d_in[0];
    const float* ew1   = (const float*)d_in[1];
    const float* eb1   = (const float*)d_in[2];
    const float* ew2   = (const float*)d_in[3];
    const float* eb2   = (const float*)d_in[4];
    const float* cb    = (const float*)d_in[5];
    const float* dw1   = (const float*)d_in[6];
    const float* db1   = (const float*)d_in[7];
    const float* dw2   = (const float*)d_in[8];
    const float* db2   = (const float*)d_in[9];

    float* out  = (float*)d_out;
    float* bhat = out;
    float* ze   = bhat + 1024000;
    float* zq   = ze   + 4096000;
    float* idxf = zq   + 4096000;
    float* loss = idxf + 128000;

    float *hid, *lpart, *cnh;
    float4 *wtp, *cbp;
    cudaGetSymbolAddress((void**)&hid,   g_hidden);
    cudaGetSymbolAddress((void**)&lpart, g_loss_part);
    cudaGetSymbolAddress((void**)&wtp,   g_wtp);
    cudaGetSymbolAddress((void**)&cbp,   g_cbp);
    cudaGetSymbolAddress((void**)&cnh,   g_cnh);

    const float4* e1p = wtp;
    const float4* e2p = wtp + 16384;
    const float4* d1p = wtp + 81920;
    const float4* d2p = wtp + 147456;

    const int SM128 = (2 * 128 * 36 + 2 * 4 * 128 * 16) * 4;   // 102400
    const int SM64  = (2 * 64 * 36 + 2 * 4 * 64 * 16) * 4;     // 51200
    cudaFuncSetAttribute((const void*)tgemm<128, 128, true,  true >,
                         cudaFuncAttributeMaxDynamicSharedMemorySize, SM128);
    cudaFuncSetAttribute((const void*)tgemm<128, 128, false, true >,
                         cudaFuncAttributeMaxDynamicSharedMemorySize, SM128);
    cudaFuncSetAttribute((const void*)tgemm<128, 128, true,  false>,
                         cudaFuncAttributeMaxDynamicSharedMemorySize, SM128);
    cudaFuncSetAttribute((const void*)tgemm<64, 64, false, false>,
                         cudaFuncAttributeMaxDynamicSharedMemorySize, SM64);
    cudaFuncSetAttribute((const void*)vq_kernel,
                         cudaFuncAttributeMaxDynamicSharedMemorySize, VQ_SMEM_FLOATS * 4);

    // Fused packed split (single launch)
    split_fused<<<672, 256>>>(ew1, ew2, dw1, dw2, cb, wtp, cbp, cnh);

    // Encoder (full 3xtf32 — feeds argmin)
    tgemm<128, 128, true,  true ><<<dim3(HIDDEN / 128, NROWS / 128), 256, SM128>>>(
        bands, e1p, eb1, hid, NROWS, HIDDEN, NBANDS);
    tgemm<128, 128, false, true ><<<dim3(LATENT / 128, NROWS / 128), 256, SM128>>>(
        hid, e2p, eb2, ze, NROWS, LATENT, HIDDEN);

    // Vector quantization (register-cached Z fragments, argmax accumulator-init)
    vq_kernel<<<dim3(NROWS / 128, GRP), 256, VQ_SMEM_FLOATS * 4>>>(
        ze, cb, cbp, cnh, zq, idxf, lpart, loss);

    // Decoder (2xtf32 — only affects bands_hat)
    tgemm<128, 128, true,  false><<<dim3(HIDDEN / 128, NROWS / 128), 256, SM128>>>(
        zq, d1p, db1, hid, NROWS, HIDDEN, LATENT);
    tgemm<64, 64, false, false><<<dim3(NBANDS / 64, NROWS / 64), 256, SM64>>>(
        hid, d2p, db2, bhat, NROWS, NBANDS, HIDDEN);
}

// round 17
// speedup vs baseline: 1.2088x; 1.0119x over previous
#include <cuda_runtime.h>
#include <cstdint>
#include <cfloat>

#define NROWS   16000
#define NBANDS  64
#define HIDDEN  512
#define LATENT  256
#define GRP     8
#define GD      32
#define KCB     1024

__device__ float g_hidden[NROWS * HIDDEN];
__device__ float g_loss_part[1024];
__device__ unsigned int g_cnt = 0;

// Packed fragment-quad weights: [kg][n][ctg] float4 = (b_k, b_k+4, r_k, r_k+4)
__device__ float4 g_wtp[163840];
// Packed codebook: [g][kg(4)][cw(1024)][ctg(4)] float4
__device__ float4 g_cbp[GRP * 16384];
__device__ float  g_cnh[GRP * KCB];          // -0.5 * ||c||^2 (exact scale)

// ===========================================================================
// Helpers
// ===========================================================================
__device__ __forceinline__ uint32_t smem_u32(const void* p) {
    uint32_t a;
    asm("{ .reg .u64 t; cvta.to.shared.u64 t, %1; cvt.u32.u64 %0, t; }" : "=r"(a) : "l"(p));
    return a;
}
__device__ __forceinline__ uint32_t tf32_of(float x) {
    uint32_t r;
    asm("cvt.rna.tf32.f32 %0, %1;" : "=r"(r) : "f"(x));
    return r;
}
__device__ __forceinline__ float tf32f(float x) {
    return __uint_as_float(tf32_of(x));
}
__device__ __forceinline__ void cp_async16(uint32_t saddr, const void* g) {
    asm volatile("cp.async.cg.shared.global [%0], [%1], 16;" :: "r"(saddr), "l"(g));
}
#define CP_COMMIT() asm volatile("cp.async.commit_group;" ::: "memory")
#define CP_WAIT0()  asm volatile("cp.async.wait_group 0;" ::: "memory")
#define CP_WAIT1()  asm volatile("cp.async.wait_group 1;" ::: "memory")

__device__ __forceinline__ void mma_tf32(float* c, const uint32_t* a, uint32_t b0, uint32_t b1) {
    asm volatile(
        "mma.sync.aligned.m16n8k8.row.col.f32.tf32.tf32.f32 "
        "{%0,%1,%2,%3}, {%4,%5,%6,%7}, {%8,%9}, {%0,%1,%2,%3};"
        : "+f"(c[0]), "+f"(c[1]), "+f"(c[2]), "+f"(c[3])
        : "r"(a[0]), "r"(a[1]), "r"(a[2]), "r"(a[3]), "r"(b0), "r"(b1));
}

// ===========================================================================
// Single fused split kernel: blocks [0,640) pack weights, [640,672) codebook.
// ===========================================================================
__global__ void split_fused(const float* __restrict__ ew1, const float* __restrict__ ew2,
                            const float* __restrict__ dw1, const float* __restrict__ dw2,
                            const float* __restrict__ cb,
                            float4* __restrict__ wtp, float4* __restrict__ cbp,
                            float* __restrict__ cnh)
{
    if (blockIdx.x < 640) {
        int i = blockIdx.x * 256 + threadIdx.x;
        const float* w; int N, off;
        if      (i < 16384)  { w = ew1; N = 512; off = i; }
        else if (i < 81920)  { w = ew2; N = 256; off = i - 16384; }
        else if (i < 147456) { w = dw1; N = 512; off = i - 81920; }
        else                 { w = dw2; N = 64;  off = i - 147456; }
        int ctg = off & 3;
        int rem = off >> 2;
        int n = rem % N, kg = rem / N;
        float x0 = w[(size_t)(kg * 8 + ctg) * N + n];
        float x1 = w[(size_t)(kg * 8 + 4 + ctg) * N + n];
        float b0 = tf32f(x0);
        float b1 = tf32f(x1);
        float r0 = tf32f(x0 - b0);
        float r1 = tf32f(x1 - b1);
        wtp[i] = make_float4(b0, b1, r0, r1);
    } else {
        int row = (blockIdx.x - 640) * 256 + threadIdx.x;
        if (row >= GRP * KCB) return;
        int g = row >> 10, cw = row & 1023;
        const float* src = cb + (size_t)row * GD;
        float bg[GD], rs[GD], s = 0.0f;
        #pragma unroll
        for (int d = 0; d < GD; d++) {
            float x = src[d];
            bg[d] = tf32f(x);
            rs[d] = tf32f(x - bg[d]);
            s = fmaf(x, x, s);
        }
        cnh[row] = -0.5f * s;
        float4* dst = cbp + (size_t)g * 16384;
        #pragma unroll
        for (int kg = 0; kg < 4; kg++)
            #pragma unroll
            for (int ctg = 0; ctg < 4; ctg++)
                dst[(kg * 1024 + cw) * 4 + ctg] =
                    make_float4(bg[kg * 8 + ctg], bg[kg * 8 + 4 + ctg],
                                rs[kg * 8 + ctg], rs[kg * 8 + 4 + ctg]);
    }
}

// ===========================================================================
// Tensor GEMM, packed-quad B, in-loop A conversion.
// FULL=true: 3xtf32 (encoder). FULL=false: 2xtf32 (decoder only).
// ===========================================================================
template<int BM, int BN, bool RELU, bool FULL>
__global__ __launch_bounds__(256, 2) void tgemm(
    const float* __restrict__ A,
    const float4* __restrict__ Wp,
    const float* __restrict__ bias, float* __restrict__ C,
    int M, int N, int K)
{
    constexpr int BK = 32;
    constexpr int ASTR = 36;
    constexpr int WN = BN / 2, NT = WN / 8;
    constexpr int MT = BM / 64;
    constexpr int ASZ = BM * ASTR;
    constexpr int BSZ4 = 4 * BN * 4;
    constexpr int A_Q = BM / 32;
    constexpr int B_Q = BN / 16;

    extern __shared__ __align__(16) float sm[];
    float*  AsBuf[2] = { sm, sm + ASZ };
    float4* BpBuf[2] = { (float4*)(sm + 2 * ASZ), (float4*)(sm + 2 * ASZ) + BSZ4 };

    const int tid = threadIdx.x;
    const int wid = tid >> 5;
    const int lane = tid & 31;
    const int grp = lane >> 2;
    const int ctg = lane & 3;
    const int wy  = wid & 3;
    const int wx  = wid >> 2;
    const int m0  = blockIdx.y * BM;
    const int n0  = blockIdx.x * BN;

    float acc[MT][NT][4];
    #pragma unroll
    for (int mt = 0; mt < MT; mt++)
        #pragma unroll
        for (int nt = 0; nt < NT; nt++)
            #pragma unroll
            for (int q = 0; q < 4; q++) acc[mt][nt][q] = 0.0f;

    auto copy_chunk = [&](int ch, int buf) {
        const int k0 = ch * BK;
        const int kg0 = ch * 4;
        uint32_t as = smem_u32(AsBuf[buf]);
        uint32_t bs = smem_u32(BpBuf[buf]);
        #pragma unroll
        for (int u = 0; u < A_Q; u++) {
            int f = tid + u * 256;
            int r = f >> 3, q = f & 7;
            cp_async16(as + (uint32_t)(r * ASTR + q * 4) * 4,
                       &A[(size_t)(m0 + r) * K + k0 + q * 4]);
        }
        #pragma unroll
        for (int u = 0; u < B_Q; u++) {
            int f = tid + u * 256;
            int kgl = f / (BN * 4);
            int rem = f % (BN * 4);
            int nl = rem >> 2, c = rem & 3;
            cp_async16(bs + (uint32_t)f * 16,
                       &Wp[((size_t)(kg0 + kgl) * N + n0 + nl) * 4 + c]);
        }
        CP_COMMIT();
    };

    auto compute = [&](int buf) {
        const float*  As = AsBuf[buf];
        const float4* Bp = BpBuf[buf];
        #pragma unroll
        for (int ks = 0; ks < 4; ks++) {
            const int k8 = ks * 8;
            uint32_t abig[MT][4], ares[MT][4];
            #pragma unroll
            for (int mt = 0; mt < MT; mt++) {
                const int rb = wy * (BM / 4) + mt * 16;
                float af[4];
                af[0] = As[(rb + grp) * ASTR + k8 + ctg];
                af[1] = As[(rb + 8 + grp) * ASTR + k8 + ctg];
                af[2] = As[(rb + grp) * ASTR + k8 + 4 + ctg];
                af[3] = As[(rb + 8 + grp) * ASTR + k8 + 4 + ctg];
                #pragma unroll
                for (int q = 0; q < 4; q++) {
                    abig[mt][q] = tf32_of(af[q]);
                    if (FULL)
                        ares[mt][q] = tf32_of(af[q] - __uint_as_float(abig[mt][q]));
                }
            }
            #pragma unroll
            for (int nt = 0; nt < NT; nt++) {
                const int col = wx * WN + nt * 8 + grp;
                float4 qd = Bp[(ks * BN + col) * 4 + ctg];
                uint32_t bb0 = __float_as_uint(qd.x);
                uint32_t bb1 = __float_as_uint(qd.y);
                uint32_t br0 = __float_as_uint(qd.z);
                uint32_t br1 = __float_as_uint(qd.w);
                #pragma unroll
                for (int mt = 0; mt < MT; mt++) {
                    mma_tf32(acc[mt][nt], abig[mt], bb0, bb1);
                    mma_tf32(acc[mt][nt], abig[mt], br0, br1);
                    if (FULL)
                        mma_tf32(acc[mt][nt], ares[mt], bb0, bb1);
                }
            }
        }
    };

    const int nch = K / BK;
    copy_chunk(0, 0);
    for (int ch = 0; ch < nch; ch++) {
        const int cur = ch & 1;
        if (ch + 1 < nch) { copy_chunk(ch + 1, cur ^ 1); CP_WAIT1(); }
        else              { CP_WAIT0(); }
        __syncthreads();
        compute(cur);
        __syncthreads();
    }

    #pragma unroll
    for (int mt = 0; mt < MT; mt++) {
        const int r0 = m0 + wy * (BM / 4) + mt * 16 + grp;
        #pragma unroll
        for (int nt = 0; nt < NT; nt++) {
            const int col = n0 + wx * WN + nt * 8 + 2 * ctg;
            float b0 = bias[col], b1 = bias[col + 1];
            float2 v0, v1;
            v0.x = acc[mt][nt][0] + b0; v0.y = acc[mt][nt][1] + b1;
            v1.x = acc[mt][nt][2] + b0; v1.y = acc[mt][nt][3] + b1;
            if (RELU) {
                v0.x = fmaxf(v0.x, 0.0f); v0.y = fmaxf(v0.y, 0.0f);
                v1.x = fmaxf(v1.x, 0.0f); v1.y = fmaxf(v1.y, 0.0f);
            }
            *(float2*)&C[(size_t)r0 * N + col] = v0;
            *(float2*)&C[(size_t)(r0 + 8) * N + col] = v1;
        }
    }
}

// ===========================================================================
// VQ kernel: register-cached Z fragments; quarter-granularity accumulators
// (acc 16 regs -> scheduling slack); last quarter's argmax deferred past the
// barrier + cp.async issue to hide copy latency. Candidate values and
// compare order identical to round-16 (nt ascending).
// ===========================================================================
#define VQ_SMEM_FLOATS 21376

__global__ __launch_bounds__(256, 2) void vq_kernel(
    const float* __restrict__ ze,
    const float* __restrict__ cb,
    const float4* __restrict__ cbp,
    const float* __restrict__ cnh,
    float* __restrict__ zq,
    float* __restrict__ idxf,
    float* __restrict__ losspart,
    float* __restrict__ lossout)
{
    extern __shared__ __align__(16) float sm[];
    float*  Zs = sm;                                       // [128][36]
    float4* CbP[2] = { (float4*)(sm + 4608), (float4*)(sm + 4608) + 2048 };
    float* CNs  = sm + 4608 + 16384;                       // [2][128] (cnh)
    float* lsum = CNs + 256;

    const int tid = threadIdx.x;
    const int wid = tid >> 5;
    const int lane = tid & 31;
    const int grp = lane >> 2;
    const int ctg = lane & 3;
    const int wy  = wid & 3;
    const int wx  = wid >> 2;
    const int g    = blockIdx.y;
    const int row0 = blockIdx.x * 128;

    const float*  zbase = ze  + (size_t)row0 * LATENT + g * GD;
    const float*  cgb   = cb  + (size_t)g * KCB * GD;
    const float4* cbpg  = cbp + (size_t)g * 16384;
    const float*  cng   = cnh + g * KCB;

    auto copyC = [&](int ch, int buf) {
        uint32_t bs = smem_u32(CbP[buf]);
        #pragma unroll
        for (int u = 0; u < 8; u++) {
            int f = tid + u * 256;
            int kgl = f >> 9;
            int rem = f & 511;
            int cwl = rem >> 2, c = rem & 3;
            cp_async16(bs + (uint32_t)f * 16,
                       &cbpg[((size_t)kgl * 1024 + ch * 128 + cwl) * 4 + c]);
        }
        if (tid < 32)
            cp_async16(smem_u32(CNs + buf * 128) + tid * 16, cng + ch * 128 + tid * 4);
    };

    {
        uint32_t zs = smem_u32(Zs);
        #pragma unroll
        for (int u = 0; u < 4; u++) {
            int f = tid + u * 256;
            int r = f >> 3, q = f & 7;
            cp_async16(zs + (uint32_t)(r * 36 + q * 4) * 4,
                       zbase + (size_t)r * LATENT + q * 4);
        }
        copyC(0, 0);
        CP_COMMIT();
        copyC(1, 1);
        CP_COMMIT();
    }
    CP_WAIT1();
    __syncthreads();

    // Convert Z fragments ONCE; hold across all chunks (64 regs).
    uint32_t abig[4][2][4], ares[4][2][4];
    #pragma unroll
    for (int ks = 0; ks < 4; ks++) {
        const int k8 = ks * 8;
        #pragma unroll
        for (int mt = 0; mt < 2; mt++) {
            const int rb = wy * 32 + mt * 16;
            float af[4];
            af[0] = Zs[(rb + grp) * 36 + k8 + ctg];
            af[1] = Zs[(rb + 8 + grp) * 36 + k8 + ctg];
            af[2] = Zs[(rb + grp) * 36 + k8 + 4 + ctg];
            af[3] = Zs[(rb + 8 + grp) * 36 + k8 + 4 + ctg];
            #pragma unroll
            for (int q = 0; q < 4; q++) {
                abig[ks][mt][q] = tf32_of(af[q]);
                ares[ks][mt][q] = tf32_of(af[q] - __uint_as_float(abig[ks][mt][q]));
            }
        }
    }

    float best[4];
    int   bidx[4];
    #pragma unroll
    for (int i = 0; i < 4; i++) { best[i] = -FLT_MAX; bidx[i] = 0; }

    // MMA for one quarter (nt = h*2 + j, j in 0..1)
    auto quarter_mma = [&](const float* CNc, const float4* Bp, int h,
                           float acc[2][2][4]) {
        #pragma unroll
        for (int j = 0; j < 2; j++) {
            const int cbase = wx * 64 + (h * 2 + j) * 8 + 2 * ctg;
            float c0 = CNc[cbase], c1 = CNc[cbase + 1];
            #pragma unroll
            for (int mt = 0; mt < 2; mt++) {
                acc[mt][j][0] = c0; acc[mt][j][1] = c1;
                acc[mt][j][2] = c0; acc[mt][j][3] = c1;
            }
        }
        #pragma unroll
        for (int ks = 0; ks < 4; ks++) {
            #pragma unroll
            for (int j = 0; j < 2; j++) {
                const int col = wx * 64 + (h * 2 + j) * 8 + grp;
                float4 qd = Bp[(ks * 128 + col) * 4 + ctg];
                uint32_t cb0 = __float_as_uint(qd.x);
                uint32_t cb1 = __float_as_uint(qd.y);
                uint32_t cr0 = __float_as_uint(qd.z);
                uint32_t cr1 = __float_as_uint(qd.w);
                #pragma unroll
                for (int mt = 0; mt < 2; mt++) {
                    mma_tf32(acc[mt][j], abig[ks][mt], cb0, cb1);
                    mma_tf32(acc[mt][j], abig[ks][mt], cr0, cr1);
                    mma_tf32(acc[mt][j], ares[ks][mt], cb0, cb1);
                }
            }
        }
    };
    auto quarter_arg = [&](int ch, int h, float acc[2][2][4]) {
        #pragma unroll
        for (int j = 0; j < 2; j++) {
            const int cbase = wx * 64 + (h * 2 + j) * 8 + 2 * ctg;
            int k0 = ch * 128 + cbase;
            #pragma unroll
            for (int mt = 0; mt < 2; mt++) {
                float v00 = acc[mt][j][0], v01 = acc[mt][j][1];
                float v10 = acc[mt][j][2], v11 = acc[mt][j][3];
                if (v00 > best[mt * 2])     { best[mt * 2] = v00;     bidx[mt * 2] = k0; }
                if (v01 > best[mt * 2])     { best[mt * 2] = v01;     bidx[mt * 2] = k0 + 1; }
                if (v10 > best[mt * 2 + 1]) { best[mt * 2 + 1] = v10; bidx[mt * 2 + 1] = k0; }
                if (v11 > best[mt * 2 + 1]) { best[mt * 2 + 1] = v11; bidx[mt * 2 + 1] = k0 + 1; }
            }
        }
    };

    int buf = 0;
    for (int ch = 0; ch < 8; ch++) {
        const float* CNc = CNs + buf * 128;
        const float4* Bp = CbP[buf];

        float acc[2][2][4];
        #pragma unroll
        for (int h = 0; h < 3; h++) {
            quarter_mma(CNc, Bp, h, acc);
            quarter_arg(ch, h, acc);
        }
        quarter_mma(CNc, Bp, 3, acc);      // last quarter MMAs
        __syncthreads();                    // all warps done reading buf
        if (ch + 2 < 8) { copyC(ch + 2, buf); CP_COMMIT(); }
        quarter_arg(ch, 3, acc);            // compares overlap cp.async flight
        if (ch + 1 < 8) {
            if (ch + 2 < 8) CP_WAIT1(); else CP_WAIT0();
            __syncthreads();
        }
        buf ^= 1;
    }

    // Cross-thread argmax reduction (8 slots/row; tie -> lowest idx)
    float* redV = (float*)CbP[0];
    int*   redI = (int*)((float*)CbP[0] + 1024);
    #pragma unroll
    for (int s = 0; s < 4; s++) {
        int row = wy * 32 + (s >> 1) * 16 + (s & 1) * 8 + grp;
        redV[row * 8 + wx * 4 + ctg] = best[s];
        redI[row * 8 + wx * 4 + ctg] = bidx[s];
    }
    __syncthreads();

    if (tid < 128) {
        int   r  = tid;
        float bv = redV[r * 8];
        int   bi = redI[r * 8];
        #pragma unroll
        for (int t = 1; t < 8; t++) {
            float v  = redV[r * 8 + t];
            int   i2 = redI[r * 8 + t];
            if (v > bv || (v == bv && i2 < bi)) { bv = v; bi = i2; }
        }
        int grow = row0 + r;
        idxf[(size_t)grow * GRP + g] = (float)bi;

        const float* cw  = cgb + (size_t)bi * GD;
        float*       zqo = zq + (size_t)grow * LATENT + g * GD;
        float diff2 = 0.0f;
        #pragma unroll
        for (int dq = 0; dq < 8; dq++) {
            float4 c4 = *(const float4*)&cw[dq * 4];
            float d0 = c4.x - Zs[r * 36 + dq * 4 + 0];
            float d1 = c4.y - Zs[r * 36 + dq * 4 + 1];
            float d2 = c4.z - Zs[r * 36 + dq * 4 + 2];
            float d3 = c4.w - Zs[r * 36 + dq * 4 + 3];
            diff2 = fmaf(d0, d0, diff2);
            diff2 = fmaf(d1, d1, diff2);
            diff2 = fmaf(d2, d2, diff2);
            diff2 = fmaf(d3, d3, diff2);
            *(float4*)&zqo[dq * 4] = c4;
        }
        lsum[r] = diff2;
    }
    __syncthreads();

    __shared__ bool is_last;
    if (tid == 0) {
        float s = 0.0f;
        for (int r = 0; r < 128; r++) s += lsum[r];
        losspart[blockIdx.y * gridDim.x + blockIdx.x] = s;
        __threadfence();
        unsigned int t = atomicAdd(&g_cnt, 1u);
        is_last = (t == (unsigned int)(gridDim.x * gridDim.y - 1));
    }
    __syncthreads();

    if (is_last) {
        int npart = gridDim.x * gridDim.y;
        float v = 0.0f;
        for (int i = tid; i < npart; i += 256) v += losspart[i];
        redV[tid] = v;
        __syncthreads();
        for (int off = 128; off > 0; off >>= 1) {
            if (tid < off) redV[tid] += redV[tid + off];
            __syncthreads();
        }
        if (tid == 0) {
            lossout[0] = redV[0] * (1.0f / 1024000.0f);
            g_cnt = 0;
        }
    }
}

// ===========================================================================
extern "C" void kernel_launch(void* const* d_in, const int* in_sizes, int n_in,
                              void* d_out, int out_size)
{
    const float* bands = (const float*)d_in[0];
    const float* ew1   = (const float*)d_in[1];
    const float* eb1   = (const float*)d_in[2];
    const float* ew2   = (const float*)d_in[3];
    const float* eb2   = (const float*)d_in[4];
    const float* cb    = (const float*)d_in[5];
    const float* dw1   = (const float*)d_in[6];
    const float* db1   = (const float*)d_in[7];
    const float* dw2   = (const float*)d_in[8];
    const float* db2   = (const float*)d_in[9];

    float* out  = (float*)d_out;
    float* bhat = out;
    float* ze   = bhat + 1024000;
    float* zq   = ze   + 4096000;
    float* idxf = zq   + 4096000;
    float* loss = idxf + 128000;

    float *hid, *lpart, *cnh;
    float4 *wtp, *cbp;
    cudaGetSymbolAddress((void**)&hid,   g_hidden);
    cudaGetSymbolAddress((void**)&lpart, g_loss_part);
    cudaGetSymbolAddress((void**)&wtp,   g_wtp);
    cudaGetSymbolAddress((void**)&cbp,   g_cbp);
    cudaGetSymbolAddress((void**)&cnh,   g_cnh);

    const float4* e1p = wtp;
    const float4* e2p = wtp + 16384;
    const float4* d1p = wtp + 81920;
    const float4* d2p = wtp + 147456;

    const int SM128 = (2 * 128 * 36 + 2 * 4 * 128 * 16) * 4;   // 102400
    const int SM64  = (2 * 64 * 36 + 2 * 4 * 64 * 16) * 4;     // 51200
    cudaFuncSetAttribute((const void*)tgemm<128, 128, true,  true >,
                         cudaFuncAttributeMaxDynamicSharedMemorySize, SM128);
    cudaFuncSetAttribute((const void*)tgemm<128, 128, false, true >,
                         cudaFuncAttributeMaxDynamicSharedMemorySize, SM128);
    cudaFuncSetAttribute((const void*)tgemm<128, 128, true,  false>,
                         cudaFuncAttributeMaxDynamicSharedMemorySize, SM128);
    cudaFuncSetAttribute((const void*)tgemm<64, 64, false, false>,
                         cudaFuncAttributeMaxDynamicSharedMemorySize, SM64);
    cudaFuncSetAttribute((const void*)vq_kernel,
                         cudaFuncAttributeMaxDynamicSharedMemorySize, VQ_SMEM_FLOATS * 4);

    // Fused packed split (single launch)
    split_fused<<<672, 256>>>(ew1, ew2, dw1, dw2, cb, wtp, cbp, cnh);

    // Encoder (full 3xtf32 — feeds argmin)
    tgemm<128, 128, true,  true ><<<dim3(HIDDEN / 128, NROWS / 128), 256, SM128>>>(
        bands, e1p, eb1, hid, NROWS, HIDDEN, NBANDS);
    tgemm<128, 128, false, true ><<<dim3(LATENT / 128, NROWS / 128), 256, SM128>>>(
        hid, e2p, eb2, ze, NROWS, LATENT, HIDDEN);

    // Vector quantization
    vq_kernel<<<dim3(NROWS / 128, GRP), 256, VQ_SMEM_FLOATS * 4>>>(
        ze, cb, cbp, cnh, zq, idxf, lpart, loss);

    // Decoder (2xtf32 — only affects bands_hat)
    tgemm<128, 128, true,  false><<<dim3(HIDDEN / 128, NROWS / 128), 256, SM128>>>(
        zq, d1p, db1, hid, NROWS, HIDDEN, LATENT);
    tgemm<64, 64, false, false><<<dim3(NBANDS / 64, NROWS / 64), 256, SM64>>>(
        hid, d2p, db2, bhat, NROWS, NBANDS, HIDDEN);
}